// round 3
// baseline (speedup 1.0000x reference)
#include <cuda_runtime.h>
#include <cuda_bf16.h>
#include <cstdint>
#include <cstddef>

#define TB      8192
#define CIN     3
#define HH      23
#define WWID    30
#define COUT    8
#define OH      22
#define OW      29
#define K1      5104
#define NF1     64
#define NS      32
#define NN      19
#define UNFOLDS 6
#define CHUNK   32
#define WARM    96
#define L2E     1.4426950408889634f

__device__ float g_act[(size_t)TB * K1 + 64];
__device__ float g_wns[(size_t)TB * NN];
__device__ float g_wds[(size_t)TB * NN];
__device__ float g_r_s2[NN * NN], g_r_c2[NN * NN], g_r_he[NN * NN], g_r_hp[NN * NN];
__device__ float g_s_s2[NS * NN], g_s_c2[NS * NN], g_s_he[NS * NN], g_s_hp[NS * NN];
__device__ float g_cmt[NN], g_Aj[NN], g_Dj[NN];

__device__ __forceinline__ float ex2f(float x) { float y; asm("ex2.approx.f32 %0, %1;" : "=f"(y) : "f"(x)); return y; }
__device__ __forceinline__ float rcpf(float x) { float y; asm("rcp.approx.f32 %0, %1;" : "=f"(y) : "f"(x)); return y; }
__device__ __forceinline__ unsigned long long pk2(float lo, float hi) {
    unsigned long long r; asm("mov.b64 %0, {%1, %2};" : "=l"(r) : "f"(lo), "f"(hi)); return r;
}
__device__ __forceinline__ void upk2(unsigned long long v, float& lo, float& hi) {
    asm("mov.b64 {%0, %1}, %2;" : "=f"(lo), "=f"(hi) : "l"(v));
}
__device__ __forceinline__ void ffma2(unsigned long long& d, unsigned long long a, unsigned long long b) {
    asm("fma.rn.f32x2 %0, %1, %2, %0;" : "+l"(d) : "l"(a), "l"(b));
}

__global__ void precompute_kernel(
    const float* __restrict__ w_, const float* __restrict__ mu_, const float* __restrict__ sig_,
    const float* __restrict__ erev_, const float* __restrict__ mask_,
    const float* __restrict__ sw, const float* __restrict__ smu, const float* __restrict__ ssig,
    const float* __restrict__ serev, const float* __restrict__ smask,
    const float* __restrict__ gleak, const float* __restrict__ vleak, const float* __restrict__ cm_)
{
    int t = threadIdx.x;
    if (t < NN * NN) {
        float wp = log1pf(expf(w_[t])) * mask_[t];
        g_r_s2[t] = -sig_[t] * L2E;
        g_r_c2[t] = sig_[t] * mu_[t] * L2E;
        g_r_he[t] = wp * erev_[t];
        g_r_hp[t] = wp;
    }
    if (t < NS * NN) {
        float sp = log1pf(expf(sw[t]));
        g_s_s2[t] = -ssig[t] * L2E;
        g_s_c2[t] = ssig[t] * smu[t] * L2E;
        g_s_he[t] = sp * serev[t];
        g_s_hp[t] = sp * smask[t];
    }
    if (t < NN) {
        float cmt = log1pf(expf(cm_[t])) * (float)UNFOLDS;
        float g = log1pf(expf(gleak[t]));
        g_cmt[t] = cmt;
        g_Aj[t] = g * vleak[t];
        g_Dj[t] = cmt + g + 1e-8f;
    }
}

__global__ __launch_bounds__(256) void conv_kernel(
    const float* __restrict__ x, const float* __restrict__ cw, const float* __restrict__ cb)
{
    __shared__ float sx[CIN * HH * WWID];
    __shared__ float swt[COUT * CIN * 4];
    __shared__ float sb[COUT];
    int b = blockIdx.x;
    const float* xb = x + (size_t)b * (CIN * HH * WWID);
    for (int i = threadIdx.x; i < CIN * HH * WWID; i += 256) sx[i] = xb[i];
    if (threadIdx.x < COUT * CIN * 4) swt[threadIdx.x] = cw[threadIdx.x];
    if (threadIdx.x < COUT) sb[threadIdx.x] = cb[threadIdx.x];
    __syncthreads();
    float* out = g_act + (size_t)b * K1;
    for (int idx = threadIdx.x; idx < COUT * OH * OW; idx += 256) {
        int c = idx / (OH * OW);
        int rem = idx - c * (OH * OW);
        int r = rem / OW;
        int col = rem - r * OW;
        float acc = sb[c];
        #pragma unroll
        for (int ci = 0; ci < CIN; ci++)
            #pragma unroll
            for (int kh = 0; kh < 2; kh++)
                #pragma unroll
                for (int kw = 0; kw < 2; kw++)
                    acc = fmaf(sx[ci * (HH * WWID) + (r + kh) * WWID + col + kw],
                               swt[((c * CIN + ci) * 2 + kh) * 2 + kw], acc);
        out[idx] = acc > 0.f ? acc : expm1f(acc);
    }
}

__global__ __launch_bounds__(256) void gemm_kernel(
    const float* __restrict__ fc1w, const float* __restrict__ fc1b,
    const float* __restrict__ fc2w, const float* __restrict__ fc2b,
    const float* __restrict__ inw, const float* __restrict__ inb)
{
    __shared__ float sAB[2 * 32 * 68];
    __shared__ float sS[64 * 33];
    __shared__ float sSen[4 * NS * NN];
    __shared__ float sF2[NS * NF1];
    __shared__ float sSm[160];
    float* sA = sAB;
    float* sB = sAB + 32 * 68;

    const int tid = threadIdx.x;
    const int m0 = blockIdx.x * 64;
    const int lm = tid >> 2;
    const int lk = (tid & 3) * 8;
    const int ty = tid >> 4;
    const int tx = tid & 15;

    for (int i = tid; i < NS * NN; i += 256) {
        sSen[i] = g_s_s2[i];
        sSen[NS * NN + i] = g_s_c2[i];
        sSen[2 * NS * NN + i] = g_s_he[i];
        sSen[3 * NS * NN + i] = g_s_hp[i];
    }
    for (int i = tid; i < NS * NF1; i += 256) sF2[i] = fc2w[i];
    if (tid < 64) sSm[tid] = fc1b[tid];
    if (tid < 32) { sSm[64 + tid] = fc2b[tid]; sSm[96 + tid] = inw[tid]; sSm[128 + tid] = inb[tid]; }

    unsigned long long acc[4][2];
    #pragma unroll
    for (int r = 0; r < 4; r++) { acc[r][0] = 0ull; acc[r][1] = 0ull; }

    const float* gA = g_act + (size_t)(m0 + lm) * K1 + lk;
    const float* gB = fc1w + (size_t)lm * K1 + lk;

    float ar[8], br[8];
    {
        float4 a0 = *(const float4*)(gA);
        float4 a1 = *(const float4*)(gA + 4);
        float4 b0 = *(const float4*)(gB);
        float4 b1 = *(const float4*)(gB + 4);
        ar[0]=a0.x; ar[1]=a0.y; ar[2]=a0.z; ar[3]=a0.w; ar[4]=a1.x; ar[5]=a1.y; ar[6]=a1.z; ar[7]=a1.w;
        br[0]=b0.x; br[1]=b0.y; br[2]=b0.z; br[3]=b0.w; br[4]=b1.x; br[5]=b1.y; br[6]=b1.z; br[7]=b1.w;
    }
    __syncthreads();

    const int NT = (K1 + 31) / 32;
    for (int kt = 0; kt < NT; ++kt) {
        #pragma unroll
        for (int u = 0; u < 8; u++) {
            sA[(lk + u) * 68 + lm] = ar[u];
            sB[(lk + u) * 68 + lm] = br[u];
        }
        __syncthreads();
        if (kt + 1 < NT) {
            const float* pA = gA + (kt + 1) * 32;
            float4 a0 = *(const float4*)(pA);
            float4 a1 = *(const float4*)(pA + 4);
            ar[0]=a0.x; ar[1]=a0.y; ar[2]=a0.z; ar[3]=a0.w; ar[4]=a1.x; ar[5]=a1.y; ar[6]=a1.z; ar[7]=a1.w;
            const float* pB = gB + (kt + 1) * 32;
            int kbase = (kt + 1) * 32 + lk;
            if (kbase + 7 < K1) {
                float4 b0 = *(const float4*)(pB);
                float4 b1 = *(const float4*)(pB + 4);
                br[0]=b0.x; br[1]=b0.y; br[2]=b0.z; br[3]=b0.w; br[4]=b1.x; br[5]=b1.y; br[6]=b1.z; br[7]=b1.w;
            } else {
                #pragma unroll
                for (int u = 0; u < 8; u++) br[u] = (kbase + u < K1) ? pB[u] : 0.f;
            }
        }
        #pragma unroll
        for (int kk = 0; kk < 32; kk++) {
            float4 av = *(const float4*)&sA[kk * 68 + ty * 4];
            float4 bv = *(const float4*)&sB[kk * 68 + tx * 4];
            unsigned long long b01 = pk2(bv.x, bv.y);
            unsigned long long b23 = pk2(bv.z, bv.w);
            unsigned long long am;
            am = pk2(av.x, av.x); ffma2(acc[0][0], am, b01); ffma2(acc[0][1], am, b23);
            am = pk2(av.y, av.y); ffma2(acc[1][0], am, b01); ffma2(acc[1][1], am, b23);
            am = pk2(av.z, av.z); ffma2(acc[2][0], am, b01); ffma2(acc[2][1], am, b23);
            am = pk2(av.w, av.w); ffma2(acc[3][0], am, b01); ffma2(acc[3][1], am, b23);
        }
        __syncthreads();
    }

    float* sOs = sAB;
    #pragma unroll
    for (int r = 0; r < 4; r++) {
        float p0, p1, p2, p3;
        upk2(acc[r][0], p0, p1);
        upk2(acc[r][1], p2, p3);
        int m = ty * 4 + r, n = tx * 4;
        sOs[m * 68 + n + 0] = fmaxf(p0 + sSm[n + 0], 0.f);
        sOs[m * 68 + n + 1] = fmaxf(p1 + sSm[n + 1], 0.f);
        sOs[m * 68 + n + 2] = fmaxf(p2 + sSm[n + 2], 0.f);
        sOs[m * 68 + n + 3] = fmaxf(p3 + sSm[n + 3], 0.f);
    }
    __syncthreads();

    {
        int row = tid >> 2, cg = tid & 3;
        for (int q = 0; q < 8; q++) {
            int n2 = cg * 8 + q;
            float a = sSm[64 + n2];
            #pragma unroll
            for (int n = 0; n < 64; n++) a = fmaf(sOs[row * 68 + n], sF2[n2 * 64 + n], a);
            sS[row * 33 + n2] = fmaf(a, sSm[96 + n2], sSm[128 + n2]);
        }
    }
    __syncthreads();

    {
        int row2 = tid & 63, jg = tid >> 6;
        for (int jj = 0; jj < 5; jj++) {
            int j = jg * 5 + jj;
            if (j < NN) {
                float wn = 0.f, wd = 0.f;
                #pragma unroll
                for (int s = 0; s < NS; s++) {
                    float e = ex2f(fmaf(sS[row2 * 33 + s], sSen[s * NN + j], sSen[NS * NN + s * NN + j]));
                    float r = rcpf(1.f + e);
                    wn = fmaf(r, sSen[2 * NS * NN + s * NN + j], wn);
                    wd = fmaf(r, sSen[3 * NS * NN + s * NN + j], wd);
                }
                g_wns[(size_t)(m0 + row2) * NN + j] = wn;
                g_wds[(size_t)(m0 + row2) * NN + j] = wd;
            }
        }
    }
}

__global__ __launch_bounds__(32) void ltc_kernel(
    const float* __restrict__ outw, const float* __restrict__ outb, float* __restrict__ out)
{
    const int c = blockIdx.x;
    const int j = threadIdx.x;
    const int jc = j < NN ? j : NN - 1;

    float s2n[NN], c2n[NN], he[NN], hp[NN];
    #pragma unroll
    for (int i = 0; i < NN; i++) {
        s2n[i] = g_r_s2[i * NN + jc];
        c2n[i] = g_r_c2[i * NN + jc];
        he[i] = g_r_he[i * NN + jc];
        hp[i] = g_r_hp[i * NN + jc];
    }
    const float cmt = g_cmt[jc], Aj = g_Aj[jc], Dj = g_Dj[jc];
    const float ow = outw[0], ob = outb[0];

    const int tout = c * CHUNK;
    int t0 = tout - WARM; if (t0 < 0) t0 = 0;
    const int tend = tout + CHUNK;

    float v = 0.f;
    float wns = g_wns[(size_t)t0 * NN + jc];
    float wds = g_wds[(size_t)t0 * NN + jc];

    for (int t = t0; t < tend; ++t) {
        float wns_n = 0.f, wds_n = 0.f;
        if (t + 1 < tend) {
            wns_n = g_wns[(size_t)(t + 1) * NN + jc];
            wds_n = g_wds[(size_t)(t + 1) * NN + jc];
        }
        #pragma unroll 1
        for (int u = 0; u < UNFOLDS; u++) {
            float wn = wns, wd = wds;
            #pragma unroll
            for (int i = 0; i < NN; i++) {
                float vi = __shfl_sync(0xffffffffu, v, i);
                float e = ex2f(fmaf(vi, s2n[i], c2n[i]));
                float r = rcpf(1.f + e);
                wn = fmaf(r, he[i], wn);
                wd = fmaf(r, hp[i], wd);
            }
            v = (fmaf(cmt, v, Aj) + wn) * rcpf(Dj + wd);
        }
        if (t >= tout && j == 0) out[t] = fmaf(v, ow, ob);
        wns = wns_n; wds = wds_n;
    }
}

extern "C" void kernel_launch(void* const* d_in, const int* in_sizes, int n_in,
                              void* d_out, int out_size) {
    const float* x      = (const float*)d_in[0];
    const float* conv_w = (const float*)d_in[1];
    const float* conv_b = (const float*)d_in[2];
    const float* fc1_w  = (const float*)d_in[3];
    const float* fc1_b  = (const float*)d_in[4];
    const float* fc2_w  = (const float*)d_in[5];
    const float* fc2_b  = (const float*)d_in[6];
    const float* inw    = (const float*)d_in[7];
    const float* inb    = (const float*)d_in[8];
    const float* sw     = (const float*)d_in[9];
    const float* smu    = (const float*)d_in[10];
    const float* ssig   = (const float*)d_in[11];
    const float* serev  = (const float*)d_in[12];
    const float* smask  = (const float*)d_in[13];
    const float* w_     = (const float*)d_in[14];
    const float* mu_    = (const float*)d_in[15];
    const float* sig_   = (const float*)d_in[16];
    const float* erev_  = (const float*)d_in[17];
    const float* mask_  = (const float*)d_in[18];
    const float* gleak  = (const float*)d_in[19];
    const float* vleak  = (const float*)d_in[20];
    const float* cm_    = (const float*)d_in[21];
    const float* outw   = (const float*)d_in[22];
    const float* outb   = (const float*)d_in[23];
    float* out = (float*)d_out;

    precompute_kernel<<<1, NS * NN>>>(w_, mu_, sig_, erev_, mask_,
                                      sw, smu, ssig, serev, smask,
                                      gleak, vleak, cm_);
    conv_kernel<<<TB, 256>>>(x, conv_w, conv_b);
    gemm_kernel<<<TB / 64, 256>>>(fc1_w, fc1_b, fc2_w, fc2_b, inw, inb);
    ltc_kernel<<<TB / CHUNK, 32>>>(outw, outb, out);
}

// round 4
// speedup vs baseline: 1.1090x; 1.1090x over previous
#include <cuda_runtime.h>
#include <cuda_bf16.h>
#include <cstdint>
#include <cstddef>

#define TB      8192
#define CIN     3
#define HH      23
#define WWID    30
#define COUT    8
#define OH      22
#define OW      29
#define K1      5104
#define NF1     64
#define NS      32
#define NN      19
#define UNFOLDS 6
#define CHUNK   16
#define WARM    32
#define L2E     1.4426950408889634f

__device__ float g_act[(size_t)TB * K1 + 64];
__device__ float g_wns[(size_t)TB * NN];
__device__ float g_wds[(size_t)TB * NN];
__device__ float g_r_s2[NN * NN], g_r_c2[NN * NN], g_r_he[NN * NN], g_r_hp[NN * NN];
__device__ float g_s_s2[NS * NN], g_s_c2[NS * NN], g_s_he[NS * NN], g_s_hp[NS * NN];
__device__ float g_cmt[NN], g_Aj[NN], g_Dj[NN];

__device__ __forceinline__ float ex2f(float x) { float y; asm("ex2.approx.f32 %0, %1;" : "=f"(y) : "f"(x)); return y; }
__device__ __forceinline__ float rcpf(float x) { float y; asm("rcp.approx.f32 %0, %1;" : "=f"(y) : "f"(x)); return y; }
__device__ __forceinline__ unsigned long long pk2(float lo, float hi) {
    unsigned long long r; asm("mov.b64 %0, {%1, %2};" : "=l"(r) : "f"(lo), "f"(hi)); return r;
}
__device__ __forceinline__ void upk2(unsigned long long v, float& lo, float& hi) {
    asm("mov.b64 {%0, %1}, %2;" : "=f"(lo), "=f"(hi) : "l"(v));
}
__device__ __forceinline__ void ffma2(unsigned long long& d, unsigned long long a, unsigned long long b) {
    asm("fma.rn.f32x2 %0, %1, %2, %0;" : "+l"(d) : "l"(a), "l"(b));
}

__global__ void precompute_kernel(
    const float* __restrict__ w_, const float* __restrict__ mu_, const float* __restrict__ sig_,
    const float* __restrict__ erev_, const float* __restrict__ mask_,
    const float* __restrict__ sw, const float* __restrict__ smu, const float* __restrict__ ssig,
    const float* __restrict__ serev, const float* __restrict__ smask,
    const float* __restrict__ gleak, const float* __restrict__ vleak, const float* __restrict__ cm_)
{
    int t = threadIdx.x;
    if (t < NN * NN) {
        float wp = log1pf(expf(w_[t])) * mask_[t];
        g_r_s2[t] = -sig_[t] * L2E;
        g_r_c2[t] = sig_[t] * mu_[t] * L2E;
        g_r_he[t] = wp * erev_[t];
        g_r_hp[t] = wp;
    }
    if (t < NS * NN) {
        float sp = log1pf(expf(sw[t]));
        g_s_s2[t] = -ssig[t] * L2E;
        g_s_c2[t] = ssig[t] * smu[t] * L2E;
        g_s_he[t] = sp * serev[t];
        g_s_hp[t] = sp * smask[t];
    }
    if (t < NN) {
        float cmt = log1pf(expf(cm_[t])) * (float)UNFOLDS;
        float g = log1pf(expf(gleak[t]));
        g_cmt[t] = cmt;
        g_Aj[t] = g * vleak[t];
        g_Dj[t] = cmt + g + 1e-8f;
    }
}

__global__ __launch_bounds__(256) void conv_kernel(
    const float* __restrict__ x, const float* __restrict__ cw, const float* __restrict__ cb)
{
    __shared__ float sx[CIN * HH * WWID];
    __shared__ float swt[COUT * CIN * 4];
    __shared__ float sb[COUT];
    int b = blockIdx.x;
    const float* xb = x + (size_t)b * (CIN * HH * WWID);
    for (int i = threadIdx.x; i < CIN * HH * WWID; i += 256) sx[i] = xb[i];
    if (threadIdx.x < COUT * CIN * 4) swt[threadIdx.x] = cw[threadIdx.x];
    if (threadIdx.x < COUT) sb[threadIdx.x] = cb[threadIdx.x];
    __syncthreads();
    float* out = g_act + (size_t)b * K1;
    for (int idx = threadIdx.x; idx < COUT * OH * OW; idx += 256) {
        int c = idx / (OH * OW);
        int rem = idx - c * (OH * OW);
        int r = rem / OW;
        int col = rem - r * OW;
        float acc = sb[c];
        #pragma unroll
        for (int ci = 0; ci < CIN; ci++)
            #pragma unroll
            for (int kh = 0; kh < 2; kh++)
                #pragma unroll
                for (int kw = 0; kw < 2; kw++)
                    acc = fmaf(sx[ci * (HH * WWID) + (r + kh) * WWID + col + kw],
                               swt[((c * CIN + ci) * 2 + kh) * 2 + kw], acc);
        out[idx] = acc > 0.f ? acc : expm1f(acc);
    }
}

// fc1 GEMM (f32x2, m-paired accumulators, duplicated-B pairs) + fused fc2 + input map + sensory
__global__ __launch_bounds__(256) void gemm_kernel(
    const float* __restrict__ fc1w, const float* __restrict__ fc1b,
    const float* __restrict__ fc2w, const float* __restrict__ fc2b,
    const float* __restrict__ inw, const float* __restrict__ inb)
{
    __shared__ __align__(16) char sraw[32 * 68 * 4 + 32 * 66 * 8];  // sA (8704B) + sB2 (16896B)
    float* sA = (float*)sraw;                                        // [32][68] floats
    unsigned long long* sB2 = (unsigned long long*)(sraw + 32 * 68 * 4); // [32][66] (b,b) pairs
    __shared__ float sS[64 * 33];
    __shared__ float sSen[4 * NS * NN];
    __shared__ float sF2[NS * NF1];
    __shared__ float sSm[160];

    const int tid = threadIdx.x;
    const int m0 = blockIdx.x * 64;
    const int lm = tid & 63;          // loader row (warp-consecutive -> conflict-free STS)
    const int lk = (tid >> 6) * 8;    // loader k-offset
    const int ty = tid >> 4;          // compute: rows ty*4..+3
    const int tx = tid & 15;          // compute: cols {2tx, 2tx+1, 2tx+32, 2tx+33}

    for (int i = tid; i < NS * NN; i += 256) {
        sSen[i] = g_s_s2[i];
        sSen[NS * NN + i] = g_s_c2[i];
        sSen[2 * NS * NN + i] = g_s_he[i];
        sSen[3 * NS * NN + i] = g_s_hp[i];
    }
    for (int i = tid; i < NS * NF1; i += 256) sF2[i] = fc2w[i];
    if (tid < 64) sSm[tid] = fc1b[tid];
    if (tid < 32) { sSm[64 + tid] = fc2b[tid]; sSm[96 + tid] = inw[tid]; sSm[128 + tid] = inb[tid]; }

    unsigned long long acc[2][4];
    #pragma unroll
    for (int p = 0; p < 2; p++)
        #pragma unroll
        for (int q = 0; q < 4; q++) acc[p][q] = 0ull;

    const float* gA = g_act + (size_t)(m0 + lm) * K1 + lk;
    const float* gB = fc1w + (size_t)lm * K1 + lk;

    float ar[8], br[8];
    {   // tile 0 (fully in-bounds)
        float4 a0 = *(const float4*)(gA);
        float4 a1 = *(const float4*)(gA + 4);
        float4 b0 = *(const float4*)(gB);
        float4 b1 = *(const float4*)(gB + 4);
        ar[0]=a0.x; ar[1]=a0.y; ar[2]=a0.z; ar[3]=a0.w; ar[4]=a1.x; ar[5]=a1.y; ar[6]=a1.z; ar[7]=a1.w;
        br[0]=b0.x; br[1]=b0.y; br[2]=b0.z; br[3]=b0.w; br[4]=b1.x; br[5]=b1.y; br[6]=b1.z; br[7]=b1.w;
    }

    auto store_tile = [&]() {
        #pragma unroll
        for (int u = 0; u < 8; u++) {
            sA[(lk + u) * 68 + lm] = ar[u];
            sB2[(lk + u) * 66 + lm] = pk2(br[u], br[u]);
        }
    };
    auto compute_tile = [&]() {
        #pragma unroll
        for (int kk = 0; kk < 32; kk++) {
            ulonglong2 av = *(const ulonglong2*)&sA[kk * 68 + ty * 4];      // m-pairs
            ulonglong2 b0 = *(const ulonglong2*)&sB2[kk * 66 + tx * 2];     // n=2tx,2tx+1
            ulonglong2 b1 = *(const ulonglong2*)&sB2[kk * 66 + tx * 2 + 32];// n=2tx+32,+33
            ffma2(acc[0][0], av.x, b0.x); ffma2(acc[0][1], av.x, b0.y);
            ffma2(acc[0][2], av.x, b1.x); ffma2(acc[0][3], av.x, b1.y);
            ffma2(acc[1][0], av.y, b0.x); ffma2(acc[1][1], av.y, b0.y);
            ffma2(acc[1][2], av.y, b1.x); ffma2(acc[1][3], av.y, b1.y);
        }
    };

    // tiles 0..157: branch-free main loop with full prefetch of kt+1
    for (int kt = 0; kt < 158; ++kt) {
        store_tile();
        __syncthreads();
        {
            const float* pA = gA + (kt + 1) * 32;
            float4 a0 = *(const float4*)(pA);
            float4 a1 = *(const float4*)(pA + 4);
            ar[0]=a0.x; ar[1]=a0.y; ar[2]=a0.z; ar[3]=a0.w; ar[4]=a1.x; ar[5]=a1.y; ar[6]=a1.z; ar[7]=a1.w;
            const float* pB = gB + (kt + 1) * 32;
            float4 b0 = *(const float4*)(pB);
            float4 b1 = *(const float4*)(pB + 4);
            br[0]=b0.x; br[1]=b0.y; br[2]=b0.z; br[3]=b0.w; br[4]=b1.x; br[5]=b1.y; br[6]=b1.z; br[7]=b1.w;
        }
        compute_tile();
        __syncthreads();
    }
    // tile 158: store+compute, ragged prefetch of tile 159 (A pad-safe; B zero-filled OOB)
    store_tile();
    __syncthreads();
    {
        const float* pA = gA + 159 * 32;
        float4 a0 = *(const float4*)(pA);
        float4 a1 = *(const float4*)(pA + 4);
        ar[0]=a0.x; ar[1]=a0.y; ar[2]=a0.z; ar[3]=a0.w; ar[4]=a1.x; ar[5]=a1.y; ar[6]=a1.z; ar[7]=a1.w;
        const float* pB = gB + 159 * 32;
        int kbase = 159 * 32 + lk;
        #pragma unroll
        for (int u = 0; u < 8; u++) br[u] = (kbase + u < K1) ? pB[u] : 0.f;
    }
    compute_tile();
    __syncthreads();
    // tile 159
    store_tile();
    __syncthreads();
    compute_tile();
    __syncthreads();

    // epilogue: relu(acc + fc1_b) into sOs (reuses staging smem; all computes done)
    float* sOs = (float*)sraw;   // [64][68]
    #pragma unroll
    for (int p = 0; p < 2; p++) {
        #pragma unroll
        for (int q = 0; q < 4; q++) {
            float c0, c1;
            upk2(acc[p][q], c0, c1);
            int m = ty * 4 + 2 * p;
            int n = (q < 2) ? (2 * tx + q) : (2 * tx + 30 + q);  // {2tx,2tx+1,2tx+32,2tx+33}
            sOs[m * 68 + n]       = fmaxf(c0 + sSm[n], 0.f);
            sOs[(m + 1) * 68 + n] = fmaxf(c1 + sSm[n], 0.f);
        }
    }
    __syncthreads();

    {   // fc2 + input affine
        int row = tid >> 2, cg = tid & 3;
        for (int q = 0; q < 8; q++) {
            int n2 = cg * 8 + q;
            float a = sSm[64 + n2];
            #pragma unroll
            for (int n = 0; n < 64; n++) a = fmaf(sOs[row * 68 + n], sF2[n2 * 64 + n], a);
            sS[row * 33 + n2] = fmaf(a, sSm[96 + n2], sSm[128 + n2]);
        }
    }
    __syncthreads();

    {   // sensory synapses
        int row2 = tid & 63, jg = tid >> 6;
        for (int jj = 0; jj < 5; jj++) {
            int j = jg * 5 + jj;
            if (j < NN) {
                float wn = 0.f, wd = 0.f;
                #pragma unroll
                for (int s = 0; s < NS; s++) {
                    float e = ex2f(fmaf(sS[row2 * 33 + s], sSen[s * NN + j], sSen[NS * NN + s * NN + j]));
                    float r = rcpf(1.f + e);
                    wn = fmaf(r, sSen[2 * NS * NN + s * NN + j], wn);
                    wd = fmaf(r, sSen[3 * NS * NN + s * NN + j], wd);
                }
                g_wns[(size_t)(m0 + row2) * NN + j] = wn;
                g_wds[(size_t)(m0 + row2) * NN + j] = wd;
            }
        }
    }
}

// LTC scan: one chunk per warp, 4 warps/block so chains spread across all 4 SMSPs
__global__ __launch_bounds__(128) void ltc_kernel(
    const float* __restrict__ outw, const float* __restrict__ outb, float* __restrict__ out)
{
    const int w = threadIdx.x >> 5;
    const int j = threadIdx.x & 31;
    const int jc = j < NN ? j : NN - 1;
    const int c = blockIdx.x * 4 + w;

    float s2n[NN], c2n[NN], he[NN], hp[NN];
    #pragma unroll
    for (int i = 0; i < NN; i++) {
        s2n[i] = g_r_s2[i * NN + jc];
        c2n[i] = g_r_c2[i * NN + jc];
        he[i] = g_r_he[i * NN + jc];
        hp[i] = g_r_hp[i * NN + jc];
    }
    const float cmt = g_cmt[jc], Aj = g_Aj[jc], Dj = g_Dj[jc];
    const float ow = outw[0], ob = outb[0];

    const int tout = c * CHUNK;
    int t0 = tout - WARM; if (t0 < 0) t0 = 0;
    const int tend = tout + CHUNK;

    float v = 0.f;
    float wns = g_wns[(size_t)t0 * NN + jc];
    float wds = g_wds[(size_t)t0 * NN + jc];

    for (int t = t0; t < tend; ++t) {
        float wns_n = 0.f, wds_n = 0.f;
        if (t + 1 < tend) {
            wns_n = g_wns[(size_t)(t + 1) * NN + jc];
            wds_n = g_wds[(size_t)(t + 1) * NN + jc];
        }
        #pragma unroll 1
        for (int u = 0; u < UNFOLDS; u++) {
            float wn = wns, wd = wds;
            #pragma unroll
            for (int i = 0; i < NN; i++) {
                float vi = __shfl_sync(0xffffffffu, v, i);
                float e = ex2f(fmaf(vi, s2n[i], c2n[i]));
                float r = rcpf(1.f + e);
                wn = fmaf(r, he[i], wn);
                wd = fmaf(r, hp[i], wd);
            }
            v = (fmaf(cmt, v, Aj) + wn) * rcpf(Dj + wd);
        }
        if (t >= tout && j == 0) out[t] = fmaf(v, ow, ob);
        wns = wns_n; wds = wds_n;
    }
}

extern "C" void kernel_launch(void* const* d_in, const int* in_sizes, int n_in,
                              void* d_out, int out_size) {
    const float* x      = (const float*)d_in[0];
    const float* conv_w = (const float*)d_in[1];
    const float* conv_b = (const float*)d_in[2];
    const float* fc1_w  = (const float*)d_in[3];
    const float* fc1_b  = (const float*)d_in[4];
    const float* fc2_w  = (const float*)d_in[5];
    const float* fc2_b  = (const float*)d_in[6];
    const float* inw    = (const float*)d_in[7];
    const float* inb    = (const float*)d_in[8];
    const float* sw     = (const float*)d_in[9];
    const float* smu    = (const float*)d_in[10];
    const float* ssig   = (const float*)d_in[11];
    const float* serev  = (const float*)d_in[12];
    const float* smask  = (const float*)d_in[13];
    const float* w_     = (const float*)d_in[14];
    const float* mu_    = (const float*)d_in[15];
    const float* sig_   = (const float*)d_in[16];
    const float* erev_  = (const float*)d_in[17];
    const float* mask_  = (const float*)d_in[18];
    const float* gleak  = (const float*)d_in[19];
    const float* vleak  = (const float*)d_in[20];
    const float* cm_    = (const float*)d_in[21];
    const float* outw   = (const float*)d_in[22];
    const float* outb   = (const float*)d_in[23];
    float* out = (float*)d_out;

    precompute_kernel<<<1, NS * NN>>>(w_, mu_, sig_, erev_, mask_,
                                      sw, smu, ssig, serev, smask,
                                      gleak, vleak, cm_);
    conv_kernel<<<TB, 256>>>(x, conv_w, conv_b);
    gemm_kernel<<<TB / 64, 256>>>(fc1_w, fc1_b, fc2_w, fc2_b, inw, inb);
    ltc_kernel<<<(TB / CHUNK) / 4, 128>>>(outw, outb, out);
}

// round 6
// speedup vs baseline: 1.7951x; 1.6187x over previous
#include <cuda_runtime.h>
#include <cuda_bf16.h>
#include <cstdint>
#include <cstddef>

#define TB      8192
#define CIN     3
#define HH      23
#define WWID    30
#define COUT    8
#define OH      22
#define OW      29
#define K1      5104
#define NF1     64
#define NS      32
#define NN      19
#define UNFOLDS 6
#define CHUNK   16
#define WARM    16
#define L2E     1.4426950408889634f

// ---- gemm config: M-tile 64, N 64, K-chunk 64 ----
#define MT      64
#define GRID_G  (TB / MT)          // 128
#define NCHUNK  80                 // ceil(5104/64)
#define SPB     136                // padded row stride in bytes (68 bf16)

__device__ float g_act[(size_t)TB * K1 + 64];
__device__ float g_wns[(size_t)TB * NN];
__device__ float g_wds[(size_t)TB * NN];
__device__ float g_r_s2[NN * NN], g_r_c2[NN * NN], g_r_he[NN * NN], g_r_hp[NN * NN];
__device__ float g_s_s2[NS * NN], g_s_c2[NS * NN], g_s_he[NS * NN], g_s_hp[NS * NN];
__device__ float g_cmt[NN], g_Aj[NN], g_Dj[NN];

__device__ __forceinline__ float ex2f(float x) { float y; asm("ex2.approx.f32 %0, %1;" : "=f"(y) : "f"(x)); return y; }
__device__ __forceinline__ float rcpf(float x) { float y; asm("rcp.approx.f32 %0, %1;" : "=f"(y) : "f"(x)); return y; }
// pack two floats to bf16x2 (lo = x, hi = y)
__device__ __forceinline__ uint32_t bf2pack(float x, float y) {
    uint32_t r; asm("cvt.rn.bf16x2.f32 %0, %1, %2;" : "=r"(r) : "f"(y), "f"(x)); return r;
}
__device__ __forceinline__ void mma16816(float* c, uint32_t a0, uint32_t a1, uint32_t a2, uint32_t a3,
                                         uint32_t b0, uint32_t b1) {
    asm volatile("mma.sync.aligned.m16n8k16.row.col.f32.bf16.bf16.f32 "
                 "{%0,%1,%2,%3}, {%4,%5,%6,%7}, {%8,%9}, {%0,%1,%2,%3};"
                 : "+f"(c[0]), "+f"(c[1]), "+f"(c[2]), "+f"(c[3])
                 : "r"(a0), "r"(a1), "r"(a2), "r"(a3), "r"(b0), "r"(b1));
}

__global__ void precompute_kernel(
    const float* __restrict__ w_, const float* __restrict__ mu_, const float* __restrict__ sig_,
    const float* __restrict__ erev_, const float* __restrict__ mask_,
    const float* __restrict__ sw, const float* __restrict__ smu, const float* __restrict__ ssig,
    const float* __restrict__ serev, const float* __restrict__ smask,
    const float* __restrict__ gleak, const float* __restrict__ vleak, const float* __restrict__ cm_)
{
    int t = threadIdx.x;
    if (t < NN * NN) {
        float wp = log1pf(expf(w_[t])) * mask_[t];
        g_r_s2[t] = -sig_[t] * L2E;
        g_r_c2[t] = sig_[t] * mu_[t] * L2E;
        g_r_he[t] = wp * erev_[t];
        g_r_hp[t] = wp;
    }
    if (t < NS * NN) {
        float sp = log1pf(expf(sw[t]));
        g_s_s2[t] = -ssig[t] * L2E;
        g_s_c2[t] = ssig[t] * smu[t] * L2E;
        g_s_he[t] = sp * serev[t];
        g_s_hp[t] = sp * smask[t];
    }
    if (t < NN) {
        float cmt = log1pf(expf(cm_[t])) * (float)UNFOLDS;
        float g = log1pf(expf(gleak[t]));
        g_cmt[t] = cmt;
        g_Aj[t] = g * vleak[t];
        g_Dj[t] = cmt + g + 1e-8f;
    }
}

__global__ __launch_bounds__(256) void conv_kernel(
    const float* __restrict__ x, const float* __restrict__ cw, const float* __restrict__ cb)
{
    __shared__ float sx[CIN * HH * WWID];
    __shared__ float swt[COUT * CIN * 4];
    __shared__ float sb[COUT];
    int b = blockIdx.x;
    const float* xb = x + (size_t)b * (CIN * HH * WWID);
    for (int i = threadIdx.x; i < CIN * HH * WWID; i += 256) sx[i] = xb[i];
    if (threadIdx.x < COUT * CIN * 4) swt[threadIdx.x] = cw[threadIdx.x];
    if (threadIdx.x < COUT) sb[threadIdx.x] = cb[threadIdx.x];
    __syncthreads();
    float* out = g_act + (size_t)b * K1;
    for (int idx = threadIdx.x; idx < COUT * OH * OW; idx += 256) {
        int c = idx / (OH * OW);
        int rem = idx - c * (OH * OW);
        int r = rem / OW;
        int col = rem - r * OW;
        float acc = sb[c];
        #pragma unroll
        for (int ci = 0; ci < CIN; ci++)
            #pragma unroll
            for (int kh = 0; kh < 2; kh++)
                #pragma unroll
                for (int kw = 0; kw < 2; kw++)
                    acc = fmaf(sx[ci * (HH * WWID) + (r + kh) * WWID + col + kw],
                               swt[((c * CIN + ci) * 2 + kh) * 2 + kw], acc);
        out[idx] = acc > 0.f ? acc : expm1f(acc);
    }
}

// fc1 via mma.sync bf16 hi/lo 3-term split + fused fc2/input/sensory epilogue
__global__ __launch_bounds__(256) void gemm_kernel(
    const float* __restrict__ fc1w, const float* __restrict__ fc1b,
    const float* __restrict__ fc2w, const float* __restrict__ fc2b,
    const float* __restrict__ inw, const float* __restrict__ inb)
{
    __shared__ __align__(16) uint8_t sStage[4 * MT * SPB];   // AH | AL | BH | BL, 8704B each
    __shared__ float sF2[NS * NF1];
    __shared__ float sSm[160];
    uint8_t* sAH = sStage;
    uint8_t* sAL = sStage + MT * SPB;
    uint8_t* sBH = sStage + 2 * MT * SPB;
    uint8_t* sBL = sStage + 3 * MT * SPB;

    const int tid = threadIdx.x;
    const int wid = tid >> 5;
    const int lid = tid & 31;
    const int gid = lid >> 2;       // fragment group id (0..7)
    const int tig = lid & 3;        // thread in group
    const int wm = wid & 3;         // M block (rows wm*16)
    const int wn = wid >> 2;        // N block (cols wn*32)
    const int m0 = blockIdx.x * MT;

    for (int i = tid; i < NS * NF1; i += 256) sF2[i] = fc2w[i];
    if (tid < 64) sSm[tid] = fc1b[tid];
    if (tid < 32) { sSm[64 + tid] = fc2b[tid]; sSm[96 + tid] = inw[tid]; sSm[128 + tid] = inb[tid]; }

    float acc[4][4];
    #pragma unroll
    for (int nb = 0; nb < 4; nb++)
        #pragma unroll
        for (int q = 0; q < 4; q++) acc[nb][q] = 0.f;

    // per-thread producer slots: 8 (row,pair) positions each for A and B
    int prow[8], ppr[8];
    #pragma unroll
    for (int u = 0; u < 8; u++) { int idx = tid + u * 256; prow[u] = idx >> 5; ppr[u] = idx & 31; }

    float2 va[8], vb[8];
    // prefetch chunk 0
    #pragma unroll
    for (int u = 0; u < 8; u++) {
        va[u] = *(const float2*)(g_act + (size_t)(m0 + prow[u]) * K1 + 2 * ppr[u]);
        vb[u] = *(const float2*)(fc1w + (size_t)prow[u] * K1 + 2 * ppr[u]);
    }

    for (int c = 0; c < NCHUNK; ++c) {
        // store chunk c (convert to bf16 hi/lo)
        #pragma unroll
        for (int u = 0; u < 8; u++) {
            uint32_t off = (uint32_t)(prow[u] * SPB + 4 * ppr[u]);
            uint32_t ah = bf2pack(va[u].x, va[u].y);
            __nv_bfloat162 ab = *reinterpret_cast<__nv_bfloat162*>(&ah);
            uint32_t al = bf2pack(va[u].x - __bfloat162float(ab.x), va[u].y - __bfloat162float(ab.y));
            *(uint32_t*)(sAH + off) = ah;
            *(uint32_t*)(sAL + off) = al;
            uint32_t bh = bf2pack(vb[u].x, vb[u].y);
            __nv_bfloat162 bb = *reinterpret_cast<__nv_bfloat162*>(&bh);
            uint32_t bl = bf2pack(vb[u].x - __bfloat162float(bb.x), vb[u].y - __bfloat162float(bb.y));
            *(uint32_t*)(sBH + off) = bh;
            *(uint32_t*)(sBL + off) = bl;
        }
        __syncthreads();
        // prefetch chunk c+1
        if (c + 1 < NCHUNK) {
            int kb = (c + 1) * 64;
            #pragma unroll
            for (int u = 0; u < 8; u++) {
                int k = kb + 2 * ppr[u];
                va[u] = *(const float2*)(g_act + (size_t)(m0 + prow[u]) * K1 + k);  // pad-safe
                vb[u] = (k < K1) ? *(const float2*)(fc1w + (size_t)prow[u] * K1 + k)
                                 : make_float2(0.f, 0.f);
            }
        }
        // compute chunk c: 4 k16-steps x 3 terms
        #pragma unroll
        for (int s = 0; s < 4; ++s) {
            const uint32_t ka = 32 * s + 4 * tig;
            const uint32_t abase = (uint32_t)((wm * 16 + gid) * SPB) + ka;
            uint32_t ah0 = *(const uint32_t*)(sAH + abase);
            uint32_t ah1 = *(const uint32_t*)(sAH + abase + 8 * SPB);
            uint32_t ah2 = *(const uint32_t*)(sAH + abase + 16);
            uint32_t ah3 = *(const uint32_t*)(sAH + abase + 8 * SPB + 16);
            uint32_t al0 = *(const uint32_t*)(sAL + abase);
            uint32_t al1 = *(const uint32_t*)(sAL + abase + 8 * SPB);
            uint32_t al2 = *(const uint32_t*)(sAL + abase + 16);
            uint32_t al3 = *(const uint32_t*)(sAL + abase + 8 * SPB + 16);
            #pragma unroll
            for (int nb = 0; nb < 4; ++nb) {
                const uint32_t bbase = (uint32_t)((wn * 32 + nb * 8 + gid) * SPB) + ka;
                uint32_t bh0 = *(const uint32_t*)(sBH + bbase);
                uint32_t bh1 = *(const uint32_t*)(sBH + bbase + 16);
                uint32_t bl0 = *(const uint32_t*)(sBL + bbase);
                uint32_t bl1 = *(const uint32_t*)(sBL + bbase + 16);
                mma16816(acc[nb], ah0, ah1, ah2, ah3, bh0, bh1);
                mma16816(acc[nb], ah0, ah1, ah2, ah3, bl0, bl1);
                mma16816(acc[nb], al0, al1, al2, al3, bh0, bh1);
            }
        }
        __syncthreads();
    }

    // ---- epilogue ----
    float* sAcc = (float*)sStage;            // [64][68] f32 (17408 B)
    float* sS   = (float*)(sStage + 17408);  // [64][33] f32 (8448 B)
    {
        int r0 = wm * 16 + gid;
        #pragma unroll
        for (int nb = 0; nb < 4; ++nb) {
            int col = wn * 32 + nb * 8 + 2 * tig;
            sAcc[r0 * 68 + col]           = fmaxf(acc[nb][0] + sSm[col], 0.f);
            sAcc[r0 * 68 + col + 1]       = fmaxf(acc[nb][1] + sSm[col + 1], 0.f);
            sAcc[(r0 + 8) * 68 + col]     = fmaxf(acc[nb][2] + sSm[col], 0.f);
            sAcc[(r0 + 8) * 68 + col + 1] = fmaxf(acc[nb][3] + sSm[col + 1], 0.f);
        }
    }
    __syncthreads();

    {   // fc2 + input affine: 4 threads per row, 8 outputs each
        int row = tid >> 2, cg = tid & 3;
        #pragma unroll
        for (int q = 0; q < 8; q++) {
            int n2 = cg * 8 + q;
            float a = sSm[64 + n2];
            #pragma unroll
            for (int n = 0; n < 64; n++) a = fmaf(sAcc[row * 68 + n], sF2[n2 * 64 + n], a);
            sS[row * 33 + n2] = fmaf(a, sSm[96 + n2], sSm[128 + n2]);
        }
    }
    __syncthreads();

    // copy sensory params over the (now free) sAcc region
    float* sp = (float*)sStage;
    for (int i = tid; i < NS * NN; i += 256) {
        sp[i] = g_s_s2[i];
        sp[NS * NN + i] = g_s_c2[i];
        sp[2 * NS * NN + i] = g_s_he[i];
        sp[3 * NS * NN + i] = g_s_hp[i];
    }
    __syncthreads();

    {   // sensory synapses
        int row2 = tid & 63, jg = tid >> 6;
        for (int jj = 0; jj < 5; jj++) {
            int j = jg * 5 + jj;
            if (j < NN) {
                float wn = 0.f, wd = 0.f;
                #pragma unroll
                for (int s2 = 0; s2 < NS; s2++) {
                    float he = sp[2 * NS * NN + s2 * NN + j];
                    float hp = sp[3 * NS * NN + s2 * NN + j];
                    if (he == 0.f && hp == 0.f) continue;
                    float e = ex2f(fmaf(sS[row2 * 33 + s2], sp[s2 * NN + j], sp[NS * NN + s2 * NN + j]));
                    float rr = rcpf(1.f + e);
                    wn = fmaf(rr, he, wn);
                    wd = fmaf(rr, hp, wd);
                }
                g_wns[(size_t)(m0 + row2) * NN + j] = wn;
                g_wds[(size_t)(m0 + row2) * NN + j] = wd;
            }
        }
    }
}

__global__ __launch_bounds__(128) void ltc_kernel(
    const float* __restrict__ outw, const float* __restrict__ outb, float* __restrict__ out)
{
    const int w = threadIdx.x >> 5;
    const int j = threadIdx.x & 31;
    const int jc = j < NN ? j : NN - 1;
    const int c = blockIdx.x * 4 + w;

    float s2n[NN], c2n[NN], he[NN], hp[NN];
    #pragma unroll
    for (int i = 0; i < NN; i++) {
        s2n[i] = g_r_s2[i * NN + jc];
        c2n[i] = g_r_c2[i * NN + jc];
        he[i] = g_r_he[i * NN + jc];
        hp[i] = g_r_hp[i * NN + jc];
    }
    const float cmt = g_cmt[jc], Aj = g_Aj[jc], Dj = g_Dj[jc];
    const float ow = outw[0], ob = outb[0];

    const int tout = c * CHUNK;
    int t0 = tout - WARM; if (t0 < 0) t0 = 0;
    const int tend = tout + CHUNK;

    float v = 0.f;
    float wns = g_wns[(size_t)t0 * NN + jc];
    float wds = g_wds[(size_t)t0 * NN + jc];

    for (int t = t0; t < tend; ++t) {
        float wns_n = 0.f, wds_n = 0.f;
        if (t + 1 < tend) {
            wns_n = g_wns[(size_t)(t + 1) * NN + jc];
            wds_n = g_wds[(size_t)(t + 1) * NN + jc];
        }
        #pragma unroll 1
        for (int u = 0; u < UNFOLDS; u++) {
            float wn = wns, wd = wds;
            #pragma unroll
            for (int i = 0; i < NN; i++) {
                float vi = __shfl_sync(0xffffffffu, v, i);
                float e = ex2f(fmaf(vi, s2n[i], c2n[i]));
                float r = rcpf(1.f + e);
                wn = fmaf(r, he[i], wn);
                wd = fmaf(r, hp[i], wd);
            }
            v = (fmaf(cmt, v, Aj) + wn) * rcpf(Dj + wd);
        }
        if (t >= tout && j == 0) out[t] = fmaf(v, ow, ob);
        wns = wns_n; wds = wds_n;
    }
}

extern "C" void kernel_launch(void* const* d_in, const int* in_sizes, int n_in,
                              void* d_out, int out_size) {
    const float* x      = (const float*)d_in[0];
    const float* conv_w = (const float*)d_in[1];
    const float* conv_b = (const float*)d_in[2];
    const float* fc1_w  = (const float*)d_in[3];
    const float* fc1_b  = (const float*)d_in[4];
    const float* fc2_w  = (const float*)d_in[5];
    const float* fc2_b  = (const float*)d_in[6];
    const float* inw    = (const float*)d_in[7];
    const float* inb    = (const float*)d_in[8];
    const float* sw     = (const float*)d_in[9];
    const float* smu    = (const float*)d_in[10];
    const float* ssig   = (const float*)d_in[11];
    const float* serev  = (const float*)d_in[12];
    const float* smask  = (const float*)d_in[13];
    const float* w_     = (const float*)d_in[14];
    const float* mu_    = (const float*)d_in[15];
    const float* sig_   = (const float*)d_in[16];
    const float* erev_  = (const float*)d_in[17];
    const float* mask_  = (const float*)d_in[18];
    const float* gleak  = (const float*)d_in[19];
    const float* vleak  = (const float*)d_in[20];
    const float* cm_    = (const float*)d_in[21];
    const float* outw   = (const float*)d_in[22];
    const float* outb   = (const float*)d_in[23];
    float* out = (float*)d_out;

    precompute_kernel<<<1, NS * NN>>>(w_, mu_, sig_, erev_, mask_,
                                      sw, smu, ssig, serev, smask,
                                      gleak, vleak, cm_);
    conv_kernel<<<TB, 256>>>(x, conv_w, conv_b);
    gemm_kernel<<<GRID_G, 256>>>(fc1_w, fc1_b, fc2_w, fc2_b, inw, inb);
    ltc_kernel<<<(TB / CHUNK) / 4, 128>>>(outw, outb, out);
}

// round 7
// speedup vs baseline: 1.9117x; 1.0649x over previous
#include <cuda_runtime.h>
#include <cuda_bf16.h>
#include <cstdint>
#include <cstddef>

#define TB      8192
#define CIN     3
#define HH      23
#define WWID    30
#define COUT    8
#define OH      22
#define OW      29
#define K1      5104
#define KP      5120               // padded K
#define NF1     64
#define NS      32
#define NN      19
#define UNFOLDS 6
#define CHUNK   16
#define WARM    16
#define L2E     1.4426950408889634f

#define MT      64
#define GRID_G  (TB / MT)          // 128
#define NCHUNK  80                 // 5120/64
#define SPB     144                // smem row stride bytes (72 bf16)

// pre-split operand storage (bf16 hi/lo)
__device__ __nv_bfloat16 g_ah[(size_t)TB * KP];
__device__ __nv_bfloat16 g_al[(size_t)TB * KP];
__device__ __nv_bfloat16 g_bh[(size_t)NF1 * KP];
__device__ __nv_bfloat16 g_bl[(size_t)NF1 * KP];
__device__ float g_wns[(size_t)TB * NN];
__device__ float g_wds[(size_t)TB * NN];
// recurrent params: exact path + tanh path
__device__ float g_r_s2[NN * NN], g_r_c2[NN * NN], g_r_he[NN * NN], g_r_hp[NN * NN];
__device__ float g_t_s[NN * NN], g_t_c[NN * NN], g_t_he[NN * NN], g_t_hp[NN * NN];
__device__ float g_bn[NN], g_bd[NN];
__device__ float g_s_s2[NS * NN], g_s_c2[NS * NN], g_s_he[NS * NN], g_s_hp[NS * NN];
__device__ float g_cmt[NN], g_Aj[NN], g_Dj[NN];

__device__ __forceinline__ float ex2f(float x) { float y; asm("ex2.approx.f32 %0, %1;" : "=f"(y) : "f"(x)); return y; }
__device__ __forceinline__ float rcpf(float x) { float y; asm("rcp.approx.f32 %0, %1;" : "=f"(y) : "f"(x)); return y; }
__device__ __forceinline__ float tanhf_a(float x) { float y; asm("tanh.approx.f32 %0, %1;" : "=f"(y) : "f"(x)); return y; }
__device__ __forceinline__ uint32_t smem_u32(const void* p) {
    uint32_t a;
    asm("{ .reg .u64 t; cvta.to.shared.u64 t, %1; cvt.u32.u64 %0, t; }" : "=r"(a) : "l"(p));
    return a;
}
__device__ __forceinline__ void ldm_x4(uint32_t* r, uint32_t addr) {
    asm volatile("ldmatrix.sync.aligned.m8n8.x4.shared.b16 {%0,%1,%2,%3}, [%4];"
                 : "=r"(r[0]), "=r"(r[1]), "=r"(r[2]), "=r"(r[3]) : "r"(addr));
}
__device__ __forceinline__ void mma16816(float* c, const uint32_t* a, uint32_t b0, uint32_t b1) {
    asm volatile("mma.sync.aligned.m16n8k16.row.col.f32.bf16.bf16.f32 "
                 "{%0,%1,%2,%3}, {%4,%5,%6,%7}, {%8,%9}, {%0,%1,%2,%3};"
                 : "+f"(c[0]), "+f"(c[1]), "+f"(c[2]), "+f"(c[3])
                 : "r"(a[0]), "r"(a[1]), "r"(a[2]), "r"(a[3]), "r"(b0), "r"(b1));
}

__global__ void precompute_kernel(
    const float* __restrict__ w_, const float* __restrict__ mu_, const float* __restrict__ sig_,
    const float* __restrict__ erev_, const float* __restrict__ mask_,
    const float* __restrict__ sw, const float* __restrict__ smu, const float* __restrict__ ssig,
    const float* __restrict__ serev, const float* __restrict__ smask,
    const float* __restrict__ gleak, const float* __restrict__ vleak, const float* __restrict__ cm_)
{
    int t = threadIdx.x;
    if (t < NN * NN) {
        float wp = log1pf(expf(w_[t])) * mask_[t];
        float sg = sig_[t], m = mu_[t];
        g_r_s2[t] = -sg * L2E;
        g_r_c2[t] = sg * m * L2E;
        g_r_he[t] = wp * erev_[t];
        g_r_hp[t] = wp;
        g_t_s[t] = 0.5f * sg;
        g_t_c[t] = -0.5f * sg * m;
        g_t_he[t] = 0.5f * wp * erev_[t];
        g_t_hp[t] = 0.5f * wp;
    }
    if (t < NS * NN) {
        float sp = log1pf(expf(sw[t]));
        g_s_s2[t] = -ssig[t] * L2E;
        g_s_c2[t] = ssig[t] * smu[t] * L2E;
        g_s_he[t] = sp * serev[t];
        g_s_hp[t] = sp * smask[t];
    }
    if (t < NN) {
        float cmt = log1pf(expf(cm_[t])) * (float)UNFOLDS;
        float g = log1pf(expf(gleak[t]));
        g_cmt[t] = cmt;
        g_Aj[t] = g * vleak[t];
        g_Dj[t] = cmt + g + 1e-8f;
        float bn = 0.f, bd = 0.f;
        for (int i = 0; i < NN; i++) {
            float wp = log1pf(expf(w_[i * NN + t])) * mask_[i * NN + t];
            bn += 0.5f * wp * erev_[i * NN + t];
            bd += 0.5f * wp;
        }
        g_bn[t] = bn;
        g_bd[t] = bd;
    }
}

// one-time B pre-split into padded bf16 hi/lo
__global__ __launch_bounds__(256) void bsplit_kernel(const float* __restrict__ fc1w) {
    int row = blockIdx.x;
    for (int k = threadIdx.x; k < KP; k += 256) {
        float v = (k < K1) ? fc1w[(size_t)row * K1 + k] : 0.f;
        __nv_bfloat16 h = __float2bfloat16(v);
        __nv_bfloat16 l = __float2bfloat16(v - __bfloat162float(h));
        g_bh[(size_t)row * KP + k] = h;
        g_bl[(size_t)row * KP + k] = l;
    }
}

// conv 2x2 + ELU, writes A pre-split bf16 hi/lo
__global__ __launch_bounds__(256) void conv_kernel(
    const float* __restrict__ x, const float* __restrict__ cw, const float* __restrict__ cb)
{
    __shared__ float sx[CIN * HH * WWID];
    __shared__ float swt[COUT * CIN * 4];
    __shared__ float sb[COUT];
    int b = blockIdx.x;
    const float* xb = x + (size_t)b * (CIN * HH * WWID);
    for (int i = threadIdx.x; i < CIN * HH * WWID; i += 256) sx[i] = xb[i];
    if (threadIdx.x < COUT * CIN * 4) swt[threadIdx.x] = cw[threadIdx.x];
    if (threadIdx.x < COUT) sb[threadIdx.x] = cb[threadIdx.x];
    __syncthreads();
    __nv_bfloat16* oh = g_ah + (size_t)b * KP;
    __nv_bfloat16* ol = g_al + (size_t)b * KP;
    for (int idx = threadIdx.x; idx < COUT * OH * OW; idx += 256) {
        int c = idx / (OH * OW);
        int rem = idx - c * (OH * OW);
        int r = rem / OW;
        int col = rem - r * OW;
        float acc = sb[c];
        #pragma unroll
        for (int ci = 0; ci < CIN; ci++)
            #pragma unroll
            for (int kh = 0; kh < 2; kh++)
                #pragma unroll
                for (int kw = 0; kw < 2; kw++)
                    acc = fmaf(sx[ci * (HH * WWID) + (r + kh) * WWID + col + kw],
                               swt[((c * CIN + ci) * 2 + kh) * 2 + kw], acc);
        float y = acc > 0.f ? acc : expm1f(acc);
        __nv_bfloat16 h = __float2bfloat16(y);
        oh[idx] = h;
        ol[idx] = __float2bfloat16(y - __bfloat162float(h));
    }
    if (threadIdx.x < KP - K1) {   // zero pad
        oh[K1 + threadIdx.x] = __float2bfloat16(0.f);
        ol[K1 + threadIdx.x] = __float2bfloat16(0.f);
    }
}

// fc1 via mma.sync + ldmatrix, pre-split operands; fused fc2/input/sensory epilogue
__global__ __launch_bounds__(256) void gemm_kernel(
    const float* __restrict__ fc1b,
    const float* __restrict__ fc2w, const float* __restrict__ fc2b,
    const float* __restrict__ inw, const float* __restrict__ inb)
{
    __shared__ __align__(16) uint8_t sStage[4 * MT * SPB];   // AH|AL|BH|BL, 9216B each
    __shared__ float sF2[NS * NF1];
    __shared__ float sSm[160];

    const int tid = threadIdx.x;
    const int wid = tid >> 5;
    const int lid = tid & 31;
    const int wm = wid & 3;
    const int wn = wid >> 2;
    const int m0 = blockIdx.x * MT;
    const uint32_t sb = smem_u32(sStage);

    for (int i = tid; i < NS * NF1; i += 256) sF2[i] = fc2w[i];
    if (tid < 64) sSm[tid] = fc1b[tid];
    if (tid < 32) { sSm[64 + tid] = fc2b[tid]; sSm[96 + tid] = inw[tid]; sSm[128 + tid] = inb[tid]; }

    // ldmatrix per-lane base addresses (byte offsets inside a 64xSPB tile)
    const uint32_t aRow = (uint32_t)((lid & 7) + 8 * ((lid >> 3) & 1));
    const uint32_t aOff = (uint32_t)((wm * 16 + aRow) * SPB + (lid >> 4) * 16);
    const uint32_t bRow0 = (uint32_t)(wn * 32 + (lid & 7) + 8 * (lid >> 4));
    const uint32_t bKh = (uint32_t)(((lid >> 3) & 1) * 16);
    const uint32_t bOff0 = bRow0 * SPB + bKh;            // nbp=0
    const uint32_t bOff1 = (bRow0 + 16) * SPB + bKh;     // nbp=1
    const uint32_t AH = sb, AL = sb + MT * SPB, BH = sb + 2 * MT * SPB, BL = sb + 3 * MT * SPB;

    // producer slots: 2 passes, 16B each, per array
    int prow[2], po8[2];
    #pragma unroll
    for (int p = 0; p < 2; p++) { int id = tid + 256 * p; prow[p] = id >> 3; po8[p] = id & 7; }

    float acc[4][4];
    #pragma unroll
    for (int nb = 0; nb < 4; nb++)
        #pragma unroll
        for (int q = 0; q < 4; q++) acc[nb][q] = 0.f;

    uint4 rah[2], ral[2], rbh[2], rbl[2];
    auto ld_chunk = [&](int c) {
        #pragma unroll
        for (int p = 0; p < 2; p++) {
            size_t ga = (size_t)(m0 + prow[p]) * KP + c * 64 + po8[p] * 8;
            size_t gb = (size_t)prow[p] * KP + c * 64 + po8[p] * 8;
            rah[p] = *(const uint4*)(g_ah + ga);
            ral[p] = *(const uint4*)(g_al + ga);
            rbh[p] = *(const uint4*)(g_bh + gb);
            rbl[p] = *(const uint4*)(g_bl + gb);
        }
    };

    ld_chunk(0);
    for (int c = 0; c < NCHUNK; ++c) {
        #pragma unroll
        for (int p = 0; p < 2; p++) {
            uint32_t so = (uint32_t)(prow[p] * SPB + po8[p] * 16);
            *(uint4*)(sStage + so) = rah[p];
            *(uint4*)(sStage + MT * SPB + so) = ral[p];
            *(uint4*)(sStage + 2 * MT * SPB + so) = rbh[p];
            *(uint4*)(sStage + 3 * MT * SPB + so) = rbl[p];
        }
        __syncthreads();
        if (c + 1 < NCHUNK) ld_chunk(c + 1);
        #pragma unroll
        for (int s = 0; s < 4; ++s) {
            const uint32_t ks = (uint32_t)(32 * s);
            uint32_t ah[4], al[4], bh[8], bl[8];
            ldm_x4(ah, AH + aOff + ks);
            ldm_x4(al, AL + aOff + ks);
            ldm_x4(bh, BH + bOff0 + ks);
            ldm_x4(bh + 4, BH + bOff1 + ks);
            ldm_x4(bl, BL + bOff0 + ks);
            ldm_x4(bl + 4, BL + bOff1 + ks);
            #pragma unroll
            for (int nb = 0; nb < 4; ++nb) {
                mma16816(acc[nb], ah, bh[2 * nb], bh[2 * nb + 1]);
                mma16816(acc[nb], ah, bl[2 * nb], bl[2 * nb + 1]);
                mma16816(acc[nb], al, bh[2 * nb], bh[2 * nb + 1]);
            }
        }
        __syncthreads();
    }

    // ---- epilogue ----
    float* sAcc = (float*)sStage;             // [64][68]
    float* sS   = (float*)(sStage + 17408);   // [64][33]
    float* sp   = (float*)(sStage + 25856);   // sensory params 4*NS*NN
    {
        int gid = lid >> 2, tig = lid & 3;
        int r0 = wm * 16 + gid;
        #pragma unroll
        for (int nb = 0; nb < 4; ++nb) {
            int col = wn * 32 + nb * 8 + 2 * tig;
            sAcc[r0 * 68 + col]           = fmaxf(acc[nb][0] + sSm[col], 0.f);
            sAcc[r0 * 68 + col + 1]       = fmaxf(acc[nb][1] + sSm[col + 1], 0.f);
            sAcc[(r0 + 8) * 68 + col]     = fmaxf(acc[nb][2] + sSm[col], 0.f);
            sAcc[(r0 + 8) * 68 + col + 1] = fmaxf(acc[nb][3] + sSm[col + 1], 0.f);
        }
    }
    for (int i = tid; i < NS * NN; i += 256) {
        sp[i] = g_s_s2[i];
        sp[NS * NN + i] = g_s_c2[i];
        sp[2 * NS * NN + i] = g_s_he[i];
        sp[3 * NS * NN + i] = g_s_hp[i];
    }
    __syncthreads();

    {   // fc2 + input affine
        int row = tid >> 2, cg = tid & 3;
        #pragma unroll
        for (int q = 0; q < 8; q++) {
            int n2 = cg * 8 + q;
            float a = sSm[64 + n2];
            #pragma unroll
            for (int n = 0; n < 64; n++) a = fmaf(sAcc[row * 68 + n], sF2[n2 * 64 + n], a);
            sS[row * 33 + n2] = fmaf(a, sSm[96 + n2], sSm[128 + n2]);
        }
    }
    __syncthreads();

    {   // sensory synapses
        int row2 = tid & 63, jg = tid >> 6;
        for (int jj = 0; jj < 5; jj++) {
            int j = jg * 5 + jj;
            if (j < NN) {
                float wn = 0.f, wd = 0.f;
                #pragma unroll
                for (int s2 = 0; s2 < NS; s2++) {
                    float he = sp[2 * NS * NN + s2 * NN + j];
                    float hp = sp[3 * NS * NN + s2 * NN + j];
                    if (he == 0.f && hp == 0.f) continue;
                    float e = ex2f(fmaf(sS[row2 * 33 + s2], sp[s2 * NN + j], sp[NS * NN + s2 * NN + j]));
                    float rr = rcpf(1.f + e);
                    wn = fmaf(rr, he, wn);
                    wd = fmaf(rr, hp, wd);
                }
                g_wns[(size_t)(m0 + row2) * NN + j] = wn;
                g_wds[(size_t)(m0 + row2) * NN + j] = wd;
            }
        }
    }
}

// LTC scan: tanh-approx warm-up (washed out), exact output phase
__global__ __launch_bounds__(128) void ltc_kernel(
    const float* __restrict__ outw, const float* __restrict__ outb, float* __restrict__ out)
{
    const int w = threadIdx.x >> 5;
    const int j = threadIdx.x & 31;
    const int jc = j < NN ? j : NN - 1;
    const int c = blockIdx.x * 4 + w;

    const float cmt = g_cmt[jc], Aj = g_Aj[jc], Dj = g_Dj[jc];
    const float ow = outw[0], ob = outb[0];

    const int tout = c * CHUNK;
    int t0 = tout - WARM; if (t0 < 0) t0 = 0;
    const int tend = tout + CHUNK;

    float v = 0.f;
    float wns = g_wns[(size_t)t0 * NN + jc];
    float wds = g_wds[(size_t)t0 * NN + jc];

    // ---- warm phase: tanh-approx sigmoid ----
    if (t0 < tout) {
        float ts[NN], tc[NN], he2[NN], hp2[NN];
        #pragma unroll
        for (int i = 0; i < NN; i++) {
            ts[i] = g_t_s[i * NN + jc];
            tc[i] = g_t_c[i * NN + jc];
            he2[i] = g_t_he[i * NN + jc];
            hp2[i] = g_t_hp[i * NN + jc];
        }
        const float bn = g_bn[jc], bd = g_bd[jc];
        for (int t = t0; t < tout; ++t) {
            float wns_n = g_wns[(size_t)(t + 1) * NN + jc];
            float wds_n = g_wds[(size_t)(t + 1) * NN + jc];
            #pragma unroll 1
            for (int u = 0; u < UNFOLDS; u++) {
                float wn = wns + bn, wd = wds + bd;
                #pragma unroll
                for (int i = 0; i < NN; i++) {
                    float vi = __shfl_sync(0xffffffffu, v, i);
                    float th = tanhf_a(fmaf(vi, ts[i], tc[i]));
                    wn = fmaf(th, he2[i], wn);
                    wd = fmaf(th, hp2[i], wd);
                }
                v = (fmaf(cmt, v, Aj) + wn) * rcpf(Dj + wd);
            }
            wns = wns_n; wds = wds_n;
        }
    }

    // ---- output phase: exact sigmoid ----
    {
        float s2n[NN], c2n[NN], he[NN], hp[NN];
        #pragma unroll
        for (int i = 0; i < NN; i++) {
            s2n[i] = g_r_s2[i * NN + jc];
            c2n[i] = g_r_c2[i * NN + jc];
            he[i] = g_r_he[i * NN + jc];
            hp[i] = g_r_hp[i * NN + jc];
        }
        for (int t = tout; t < tend; ++t) {
            float wns_n = 0.f, wds_n = 0.f;
            if (t + 1 < tend) {
                wns_n = g_wns[(size_t)(t + 1) * NN + jc];
                wds_n = g_wds[(size_t)(t + 1) * NN + jc];
            }
            #pragma unroll 1
            for (int u = 0; u < UNFOLDS; u++) {
                float wn = wns, wd = wds;
                #pragma unroll
                for (int i = 0; i < NN; i++) {
                    float vi = __shfl_sync(0xffffffffu, v, i);
                    float e = ex2f(fmaf(vi, s2n[i], c2n[i]));
                    float r = rcpf(1.f + e);
                    wn = fmaf(r, he[i], wn);
                    wd = fmaf(r, hp[i], wd);
                }
                v = (fmaf(cmt, v, Aj) + wn) * rcpf(Dj + wd);
            }
            if (j == 0) out[t] = fmaf(v, ow, ob);
            wns = wns_n; wds = wds_n;
        }
    }
}

extern "C" void kernel_launch(void* const* d_in, const int* in_sizes, int n_in,
                              void* d_out, int out_size) {
    const float* x      = (const float*)d_in[0];
    const float* conv_w = (const float*)d_in[1];
    const float* conv_b = (const float*)d_in[2];
    const float* fc1_w  = (const float*)d_in[3];
    const float* fc1_b  = (const float*)d_in[4];
    const float* fc2_w  = (const float*)d_in[5];
    const float* fc2_b  = (const float*)d_in[6];
    const float* inw    = (const float*)d_in[7];
    const float* inb    = (const float*)d_in[8];
    const float* sw     = (const float*)d_in[9];
    const float* smu    = (const float*)d_in[10];
    const float* ssig   = (const float*)d_in[11];
    const float* serev  = (const float*)d_in[12];
    const float* smask  = (const float*)d_in[13];
    const float* w_     = (const float*)d_in[14];
    const float* mu_    = (const float*)d_in[15];
    const float* sig_   = (const float*)d_in[16];
    const float* erev_  = (const float*)d_in[17];
    const float* mask_  = (const float*)d_in[18];
    const float* gleak  = (const float*)d_in[19];
    const float* vleak  = (const float*)d_in[20];
    const float* cm_    = (const float*)d_in[21];
    const float* outw   = (const float*)d_in[22];
    const float* outb   = (const float*)d_in[23];
    float* out = (float*)d_out;

    precompute_kernel<<<1, NS * NN>>>(w_, mu_, sig_, erev_, mask_,
                                      sw, smu, ssig, serev, smask,
                                      gleak, vleak, cm_);
    bsplit_kernel<<<NF1, 256>>>(fc1_w);
    conv_kernel<<<TB, 256>>>(x, conv_w, conv_b);
    gemm_kernel<<<GRID_G, 256>>>(fc1_b, fc2_w, fc2_b, inw, inb);
    ltc_kernel<<<(TB / CHUNK) / 4, 128>>>(outw, outb, out);
}

// round 9
// speedup vs baseline: 2.0772x; 1.0866x over previous
#include <cuda_runtime.h>
#include <cuda_bf16.h>
#include <cstdint>
#include <cstddef>

#define TB      8192
#define CIN     3
#define HH      23
#define WWID    30
#define COUT    8
#define OH      22
#define OW      29
#define K1      5104
#define KP      5120
#define NF1     64
#define NS      32
#define NN      19
#define UNFOLDS 6
#define CHUNK   16
#define WARM    8
#define L2E     1.4426950408889634f

#define MT      64
#define NCHUNK  80
#define SPLITK  4
#define CPS     (NCHUNK / SPLITK)   // 20 chunks per split
#define SPB     144

__device__ __nv_bfloat16 g_ah[(size_t)TB * KP];
__device__ __nv_bfloat16 g_al[(size_t)TB * KP];
__device__ __nv_bfloat16 g_bh[(size_t)NF1 * KP];
__device__ __nv_bfloat16 g_bl[(size_t)NF1 * KP];
__device__ float g_part[(size_t)SPLITK * TB * NF1];
__device__ float g_wns[(size_t)TB * NN];
__device__ float g_wds[(size_t)TB * NN];
__device__ float g_r_s2[NN * NN], g_r_c2[NN * NN], g_r_he[NN * NN], g_r_hp[NN * NN];
__device__ float g_s_s2[NS * NN], g_s_c2[NS * NN], g_s_he[NS * NN], g_s_hp[NS * NN];
__device__ float g_cmt[NN], g_Aj[NN], g_Dj[NN];

__device__ __forceinline__ float ex2f(float x) { float y; asm("ex2.approx.f32 %0, %1;" : "=f"(y) : "f"(x)); return y; }
__device__ __forceinline__ float rcpf(float x) { float y; asm("rcp.approx.f32 %0, %1;" : "=f"(y) : "f"(x)); return y; }
__device__ __forceinline__ uint32_t smem_u32(const void* p) {
    uint32_t a;
    asm("{ .reg .u64 t; cvta.to.shared.u64 t, %1; cvt.u32.u64 %0, t; }" : "=r"(a) : "l"(p));
    return a;
}
__device__ __forceinline__ void ldm_x4(uint32_t* r, uint32_t addr) {
    asm volatile("ldmatrix.sync.aligned.m8n8.x4.shared.b16 {%0,%1,%2,%3}, [%4];"
                 : "=r"(r[0]), "=r"(r[1]), "=r"(r[2]), "=r"(r[3]) : "r"(addr));
}
__device__ __forceinline__ void mma16816(float* c, const uint32_t* a, uint32_t b0, uint32_t b1) {
    asm volatile("mma.sync.aligned.m16n8k16.row.col.f32.bf16.bf16.f32 "
                 "{%0,%1,%2,%3}, {%4,%5,%6,%7}, {%8,%9}, {%0,%1,%2,%3};"
                 : "+f"(c[0]), "+f"(c[1]), "+f"(c[2]), "+f"(c[3])
                 : "r"(a[0]), "r"(a[1]), "r"(a[2]), "r"(a[3]), "r"(b0), "r"(b1));
}

__global__ void precompute_kernel(
    const float* __restrict__ w_, const float* __restrict__ mu_, const float* __restrict__ sig_,
    const float* __restrict__ erev_, const float* __restrict__ mask_,
    const float* __restrict__ sw, const float* __restrict__ smu, const float* __restrict__ ssig,
    const float* __restrict__ serev, const float* __restrict__ smask,
    const float* __restrict__ gleak, const float* __restrict__ vleak, const float* __restrict__ cm_)
{
    int t = threadIdx.x;
    if (t < NN * NN) {
        float wp = log1pf(expf(w_[t])) * mask_[t];
        g_r_s2[t] = -sig_[t] * L2E;
        g_r_c2[t] = sig_[t] * mu_[t] * L2E;
        g_r_he[t] = wp * erev_[t];
        g_r_hp[t] = wp;
    }
    if (t < NS * NN) {
        float sp = log1pf(expf(sw[t]));
        g_s_s2[t] = -ssig[t] * L2E;
        g_s_c2[t] = ssig[t] * smu[t] * L2E;
        g_s_he[t] = sp * serev[t];
        g_s_hp[t] = sp * smask[t];
    }
    if (t < NN) {
        float cmt = log1pf(expf(cm_[t])) * (float)UNFOLDS;
        float g = log1pf(expf(gleak[t]));
        g_cmt[t] = cmt;
        g_Aj[t] = g * vleak[t];
        g_Dj[t] = cmt + g + 1e-8f;
    }
}

__global__ __launch_bounds__(256) void bsplit_kernel(const float* __restrict__ fc1w) {
    int row = blockIdx.x;
    for (int k = threadIdx.x; k < KP; k += 256) {
        float v = (k < K1) ? fc1w[(size_t)row * K1 + k] : 0.f;
        __nv_bfloat16 h = __float2bfloat16(v);
        __nv_bfloat16 l = __float2bfloat16(v - __bfloat162float(h));
        g_bh[(size_t)row * KP + k] = h;
        g_bl[(size_t)row * KP + k] = l;
    }
}

__global__ __launch_bounds__(256) void conv_kernel(
    const float* __restrict__ x, const float* __restrict__ cw, const float* __restrict__ cb)
{
    __shared__ float sx[CIN * HH * WWID];
    __shared__ float swt[COUT * CIN * 4];
    __shared__ float sb[COUT];
    int b = blockIdx.x;
    const float* xb = x + (size_t)b * (CIN * HH * WWID);
    for (int i = threadIdx.x; i < CIN * HH * WWID; i += 256) sx[i] = xb[i];
    if (threadIdx.x < COUT * CIN * 4) swt[threadIdx.x] = cw[threadIdx.x];
    if (threadIdx.x < COUT) sb[threadIdx.x] = cb[threadIdx.x];
    __syncthreads();
    __nv_bfloat16* oh = g_ah + (size_t)b * KP;
    __nv_bfloat16* ol = g_al + (size_t)b * KP;
    for (int idx = threadIdx.x; idx < COUT * OH * OW; idx += 256) {
        int c = idx / (OH * OW);
        int rem = idx - c * (OH * OW);
        int r = rem / OW;
        int col = rem - r * OW;
        float acc = sb[c];
        #pragma unroll
        for (int ci = 0; ci < CIN; ci++)
            #pragma unroll
            for (int kh = 0; kh < 2; kh++)
                #pragma unroll
                for (int kw = 0; kw < 2; kw++)
                    acc = fmaf(sx[ci * (HH * WWID) + (r + kh) * WWID + col + kw],
                               swt[((c * CIN + ci) * 2 + kh) * 2 + kw], acc);
        float y = acc > 0.f ? acc : expm1f(acc);
        __nv_bfloat16 h = __float2bfloat16(y);
        oh[idx] = h;
        ol[idx] = __float2bfloat16(y - __bfloat162float(h));
    }
    if (threadIdx.x < KP - K1) {
        oh[K1 + threadIdx.x] = __float2bfloat16(0.f);
        ol[K1 + threadIdx.x] = __float2bfloat16(0.f);
    }
}

// fc1 split-K GEMM: grid (128, SPLITK); writes fp32 partials
__global__ __launch_bounds__(256) void gemm_kernel()
{
    __shared__ __align__(16) uint8_t sStage[4 * MT * SPB];   // 36,864 B

    const int tid = threadIdx.x;
    const int wid = tid >> 5;
    const int lid = tid & 31;
    const int wm = wid & 3;
    const int wn = wid >> 2;
    const int m0 = blockIdx.x * MT;
    const int c0 = blockIdx.y * CPS;
    const uint32_t sb = smem_u32(sStage);

    const uint32_t aRow = (uint32_t)((lid & 7) + 8 * ((lid >> 3) & 1));
    const uint32_t aOff = (uint32_t)((wm * 16 + aRow) * SPB + (lid >> 4) * 16);
    const uint32_t bRow0 = (uint32_t)(wn * 32 + (lid & 7) + 8 * (lid >> 4));
    const uint32_t bKh = (uint32_t)(((lid >> 3) & 1) * 16);
    const uint32_t bOff0 = bRow0 * SPB + bKh;
    const uint32_t bOff1 = (bRow0 + 16) * SPB + bKh;
    const uint32_t AH = sb, AL = sb + MT * SPB, BH = sb + 2 * MT * SPB, BL = sb + 3 * MT * SPB;

    int prow[2], po8[2];
    #pragma unroll
    for (int p = 0; p < 2; p++) { int id = tid + 256 * p; prow[p] = id >> 3; po8[p] = id & 7; }

    float acc[4][4];
    #pragma unroll
    for (int nb = 0; nb < 4; nb++)
        #pragma unroll
        for (int q = 0; q < 4; q++) acc[nb][q] = 0.f;

    uint4 rah[2], ral[2], rbh[2], rbl[2];
    auto ld_chunk = [&](int c) {
        #pragma unroll
        for (int p = 0; p < 2; p++) {
            size_t ga = (size_t)(m0 + prow[p]) * KP + c * 64 + po8[p] * 8;
            size_t gb = (size_t)prow[p] * KP + c * 64 + po8[p] * 8;
            rah[p] = *(const uint4*)(g_ah + ga);
            ral[p] = *(const uint4*)(g_al + ga);
            rbh[p] = *(const uint4*)(g_bh + gb);
            rbl[p] = *(const uint4*)(g_bl + gb);
        }
    };

    ld_chunk(c0);
    for (int ci = 0; ci < CPS; ++ci) {
        #pragma unroll
        for (int p = 0; p < 2; p++) {
            uint32_t so = (uint32_t)(prow[p] * SPB + po8[p] * 16);
            *(uint4*)(sStage + so) = rah[p];
            *(uint4*)(sStage + MT * SPB + so) = ral[p];
            *(uint4*)(sStage + 2 * MT * SPB + so) = rbh[p];
            *(uint4*)(sStage + 3 * MT * SPB + so) = rbl[p];
        }
        __syncthreads();
        if (ci + 1 < CPS) ld_chunk(c0 + ci + 1);
        #pragma unroll
        for (int s = 0; s < 4; ++s) {
            const uint32_t ks = (uint32_t)(32 * s);
            uint32_t ah[4], al[4], bh[8], bl[8];
            ldm_x4(ah, AH + aOff + ks);
            ldm_x4(al, AL + aOff + ks);
            ldm_x4(bh, BH + bOff0 + ks);
            ldm_x4(bh + 4, BH + bOff1 + ks);
            ldm_x4(bl, BL + bOff0 + ks);
            ldm_x4(bl + 4, BL + bOff1 + ks);
            #pragma unroll
            for (int nb = 0; nb < 4; ++nb) {
                mma16816(acc[nb], ah, bh[2 * nb], bh[2 * nb + 1]);
                mma16816(acc[nb], ah, bl[2 * nb], bl[2 * nb + 1]);
                mma16816(acc[nb], al, bh[2 * nb], bh[2 * nb + 1]);
            }
        }
        __syncthreads();
    }

    // store fp32 partials
    {
        int gid = lid >> 2, tig = lid & 3;
        int r0 = wm * 16 + gid;
        float* pb = g_part + ((size_t)blockIdx.y * TB + m0) * NF1;
        #pragma unroll
        for (int nb = 0; nb < 4; ++nb) {
            int col = wn * 32 + nb * 8 + 2 * tig;
            *(float2*)(pb + (size_t)r0 * NF1 + col) = make_float2(acc[nb][0], acc[nb][1]);
            *(float2*)(pb + (size_t)(r0 + 8) * NF1 + col) = make_float2(acc[nb][2], acc[nb][3]);
        }
    }
}

// epilogue: sum partials -> relu(fc1) -> fc2 -> input affine -> sensory synapses
__global__ __launch_bounds__(256) void epi_kernel(
    const float* __restrict__ fc1b,
    const float* __restrict__ fc2w, const float* __restrict__ fc2b,
    const float* __restrict__ inw, const float* __restrict__ inb)
{
    __shared__ float sAcc[64 * 68];
    __shared__ float sS[64 * 33];
    __shared__ float sF2[NS * NF1];
    __shared__ float sSm[160];
    __shared__ float sp[4 * NS * NN];

    const int tid = threadIdx.x;
    const int m0 = blockIdx.x * 64;

    for (int i = tid; i < NS * NF1; i += 256) sF2[i] = fc2w[i];
    if (tid < 64) sSm[tid] = fc1b[tid];
    if (tid < 32) { sSm[64 + tid] = fc2b[tid]; sSm[96 + tid] = inw[tid]; sSm[128 + tid] = inb[tid]; }
    for (int i = tid; i < NS * NN; i += 256) {
        sp[i] = g_s_s2[i];
        sp[NS * NN + i] = g_s_c2[i];
        sp[2 * NS * NN + i] = g_s_he[i];
        sp[3 * NS * NN + i] = g_s_hp[i];
    }

    for (int idx = tid; idx < 64 * 16; idx += 256) {
        int row = idx >> 4, c4 = (idx & 15) * 4;
        float4 a = make_float4(0.f, 0.f, 0.f, 0.f);
        #pragma unroll
        for (int s = 0; s < SPLITK; s++) {
            float4 v = *(const float4*)(g_part + ((size_t)s * TB + m0 + row) * NF1 + c4);
            a.x += v.x; a.y += v.y; a.z += v.z; a.w += v.w;
        }
        sAcc[row * 68 + c4 + 0] = fmaxf(a.x + sSm[c4 + 0], 0.f);
        sAcc[row * 68 + c4 + 1] = fmaxf(a.y + sSm[c4 + 1], 0.f);
        sAcc[row * 68 + c4 + 2] = fmaxf(a.z + sSm[c4 + 2], 0.f);
        sAcc[row * 68 + c4 + 3] = fmaxf(a.w + sSm[c4 + 3], 0.f);
    }
    __syncthreads();

    {   // fc2 + input affine
        int row = tid >> 2, cg = tid & 3;
        #pragma unroll
        for (int q = 0; q < 8; q++) {
            int n2 = cg * 8 + q;
            float a = sSm[64 + n2];
            #pragma unroll
            for (int n = 0; n < 64; n++) a = fmaf(sAcc[row * 68 + n], sF2[n2 * 64 + n], a);
            sS[row * 33 + n2] = fmaf(a, sSm[96 + n2], sSm[128 + n2]);
        }
    }
    __syncthreads();

    {   // sensory synapses
        int row2 = tid & 63, jg = tid >> 6;
        for (int jj = 0; jj < 5; jj++) {
            int j = jg * 5 + jj;
            if (j < NN) {
                float wn = 0.f, wd = 0.f;
                #pragma unroll
                for (int s2 = 0; s2 < NS; s2++) {
                    float he = sp[2 * NS * NN + s2 * NN + j];
                    float hp = sp[3 * NS * NN + s2 * NN + j];
                    if (he == 0.f && hp == 0.f) continue;
                    float e = ex2f(fmaf(sS[row2 * 33 + s2], sp[s2 * NN + j], sp[NS * NN + s2 * NN + j]));
                    float rr = rcpf(1.f + e);
                    wn = fmaf(rr, he, wn);
                    wd = fmaf(rr, hp, wd);
                }
                g_wns[(size_t)(m0 + row2) * NN + j] = wn;
                g_wds[(size_t)(m0 + row2) * NN + j] = wd;
            }
        }
    }
}

// LTC scan: single exact-sigmoid path, WARM=8
__global__ __launch_bounds__(128) void ltc_kernel(
    const float* __restrict__ outw, const float* __restrict__ outb, float* __restrict__ out)
{
    const int w = threadIdx.x >> 5;
    const int j = threadIdx.x & 31;
    const int jc = j < NN ? j : NN - 1;
    const int c = blockIdx.x * 4 + w;

    float s2n[NN], c2n[NN], he[NN], hp[NN];
    #pragma unroll
    for (int i = 0; i < NN; i++) {
        s2n[i] = g_r_s2[i * NN + jc];
        c2n[i] = g_r_c2[i * NN + jc];
        he[i] = g_r_he[i * NN + jc];
        hp[i] = g_r_hp[i * NN + jc];
    }
    const float cmt = g_cmt[jc], Aj = g_Aj[jc], Dj = g_Dj[jc];
    const float ow = outw[0], ob = outb[0];

    const int tout = c * CHUNK;
    int t0 = tout - WARM; if (t0 < 0) t0 = 0;
    const int tend = tout + CHUNK;

    float v = 0.f;
    float wns = g_wns[(size_t)t0 * NN + jc];
    float wds = g_wds[(size_t)t0 * NN + jc];

    for (int t = t0; t < tend; ++t) {
        float wns_n = 0.f, wds_n = 0.f;
        if (t + 1 < tend) {
            wns_n = g_wns[(size_t)(t + 1) * NN + jc];
            wds_n = g_wds[(size_t)(t + 1) * NN + jc];
        }
        #pragma unroll 1
        for (int u = 0; u < UNFOLDS; u++) {
            float wn = wns, wd = wds;
            #pragma unroll
            for (int i = 0; i < NN; i++) {
                float vi = __shfl_sync(0xffffffffu, v, i);
                float e = ex2f(fmaf(vi, s2n[i], c2n[i]));
                float r = rcpf(1.f + e);
                wn = fmaf(r, he[i], wn);
                wd = fmaf(r, hp[i], wd);
            }
            v = (fmaf(cmt, v, Aj) + wn) * rcpf(Dj + wd);
        }
        if (t >= tout && j == 0) out[t] = fmaf(v, ow, ob);
        wns = wns_n; wds = wds_n;
    }
}

extern "C" void kernel_launch(void* const* d_in, const int* in_sizes, int n_in,
                              void* d_out, int out_size) {
    const float* x      = (const float*)d_in[0];
    const float* conv_w = (const float*)d_in[1];
    const float* conv_b = (const float*)d_in[2];
    const float* fc1_w  = (const float*)d_in[3];
    const float* fc1_b  = (const float*)d_in[4];
    const float* fc2_w  = (const float*)d_in[5];
    const float* fc2_b  = (const float*)d_in[6];
    const float* inw    = (const float*)d_in[7];
    const float* inb    = (const float*)d_in[8];
    const float* sw     = (const float*)d_in[9];
    const float* smu    = (const float*)d_in[10];
    const float* ssig   = (const float*)d_in[11];
    const float* serev  = (const float*)d_in[12];
    const float* smask  = (const float*)d_in[13];
    const float* w_     = (const float*)d_in[14];
    const float* mu_    = (const float*)d_in[15];
    const float* sig_   = (const float*)d_in[16];
    const float* erev_  = (const float*)d_in[17];
    const float* mask_  = (const float*)d_in[18];
    const float* gleak  = (const float*)d_in[19];
    const float* vleak  = (const float*)d_in[20];
    const float* cm_    = (const float*)d_in[21];
    const float* outw   = (const float*)d_in[22];
    const float* outb   = (const float*)d_in[23];
    float* out = (float*)d_out;

    precompute_kernel<<<1, NS * NN>>>(w_, mu_, sig_, erev_, mask_,
                                      sw, smu, ssig, serev, smask,
                                      gleak, vleak, cm_);
    bsplit_kernel<<<NF1, 256>>>(fc1_w);
    conv_kernel<<<TB, 256>>>(x, conv_w, conv_b);
    gemm_kernel<<<dim3(TB / MT, SPLITK), 256>>>();
    epi_kernel<<<TB / 64, 256>>>(fc1_b, fc2_w, fc2_b, inw, inb);
    ltc_kernel<<<(TB / CHUNK) / 4, 128>>>(outw, outb, out);
}